// round 5
// baseline (speedup 1.0000x reference)
#include <cuda_runtime.h>
#include <math.h>
#include <float.h>

// Problem constants (fixed by setup_inputs)
#define D        768
#define HW       1024          // 32*32
#define NB       4
#define NQ       4096          // NB*HW
#define NDB      20000
#define OUT_H    512
#define OUT_W    512

// GEMM tiling
#define QT       64
#define NT       64
#define KT       16
#define NCHUNKS  8
#define NTILES   ((NDB + NT - 1) / NT)   // 313

// Scratch (no allocations allowed -> device globals)
__device__ float g_x2[NDB];
__device__ float g_q2[NQ];
__device__ float g_partial[NQ * NCHUNKS * 3];
__device__ float g_ood[NQ];

// ---------------------------------------------------------------------------
// database row norms: one warp per row
// ---------------------------------------------------------------------------
__global__ void db_norms_kernel(const float* __restrict__ db) {
    int row  = blockIdx.x * (blockDim.x >> 5) + (threadIdx.x >> 5);
    int lane = threadIdx.x & 31;
    if (row >= NDB) return;
    const float* r = db + (size_t)row * D;
    float s = 0.f;
    #pragma unroll 4
    for (int d = lane; d < D; d += 32) { float v = r[d]; s = fmaf(v, v, s); }
    #pragma unroll
    for (int o = 16; o; o >>= 1) s += __shfl_down_sync(0xffffffffu, s, o);
    if (lane == 0) g_x2[row] = s;
}

// ---------------------------------------------------------------------------
// query norms: one thread per query, loop over D (coalesced across pixels)
// ---------------------------------------------------------------------------
__global__ void q_norms_kernel(const float* __restrict__ emb) {
    int q = blockIdx.x * blockDim.x + threadIdx.x;
    if (q >= NQ) return;
    int b = q >> 10;
    int p = q & 1023;
    const float* e = emb + (size_t)b * D * HW + p;
    float s = 0.f;
    #pragma unroll 8
    for (int d = 0; d < D; ++d) { float v = e[(size_t)d * HW]; s = fmaf(v, v, s); }
    g_q2[q] = s;
}

// ---------------------------------------------------------------------------
// Fused distance GEMM + per-chunk top-3.
// Block: 256 threads, computes a 64(query) x 64(db) dot tile, 4x4 per thread.
// Grid: (NQ/QT, NCHUNKS); block handles db tiles t = y, y+8, ...
// Ranking key: s = ||x||^2 - 2*q.x  (||q||^2 constant per query).
// ---------------------------------------------------------------------------
struct alignas(16) TileSmem {
    float As[KT][QT + 4];   // +4 keeps float4 alignment (row = 68 floats)
    float Bs[KT][NT + 4];
};
union alignas(16) GemmSmem {
    TileSmem t;
    float merge[QT][16][3];
};

__device__ __forceinline__ void insert3(float s, float& b0, float& b1, float& b2) {
    if (s < b2) {
        if (s < b1) {
            b2 = b1;
            if (s < b0) { b1 = b0; b0 = s; }
            else        { b1 = s; }
        } else {
            b2 = s;
        }
    }
}

__global__ void __launch_bounds__(256) knn_gemm_kernel(const float* __restrict__ emb,
                                                       const float* __restrict__ db) {
    __shared__ GemmSmem sm;

    const int tid = threadIdx.x;
    const int tx  = tid & 15;   // db-column group
    const int ty  = tid >> 4;   // query-row group

    const int q0 = blockIdx.x * QT;
    const int b  = q0 >> 10;          // 1024 % 64 == 0 -> tile within one batch
    const int p0 = q0 & 1023;
    const float* embB = emb + (size_t)b * D * HW;

    // loader lanes
    const int a_k = tid >> 6;         // 0..3
    const int a_q = tid & 63;         // 0..63
    const int b_d = tid & 15;         // 0..15
    const int b_n = tid >> 4;         // 0..15

    float best[4][3];
    #pragma unroll
    for (int i = 0; i < 4; ++i)
        best[i][0] = best[i][1] = best[i][2] = FLT_MAX;

    for (int t = blockIdx.y; t < NTILES; t += NCHUNKS) {
        const int n0 = t * NT;
        float acc[4][4];
        #pragma unroll
        for (int i = 0; i < 4; ++i)
            #pragma unroll
            for (int j = 0; j < 4; ++j) acc[i][j] = 0.f;

        for (int k0 = 0; k0 < D; k0 += KT) {
            // Load query tile (coalesced: consecutive threads -> consecutive pixels)
            #pragma unroll
            for (int i = 0; i < 4; ++i) {
                int kk = a_k + 4 * i;
                sm.t.As[kk][a_q] = embB[(size_t)(k0 + kk) * HW + p0 + a_q];
            }
            // Load db tile (16 consecutive floats per row per 16 threads)
            #pragma unroll
            for (int i = 0; i < 4; ++i) {
                int nn = b_n + 16 * i;
                int n  = n0 + nn;
                sm.t.Bs[b_d][nn] = (n < NDB) ? db[(size_t)n * D + k0 + b_d] : 0.f;
            }
            __syncthreads();
            #pragma unroll
            for (int kk = 0; kk < KT; ++kk) {
                float4 aq = *reinterpret_cast<const float4*>(&sm.t.As[kk][ty * 4]);
                float4 bn = *reinterpret_cast<const float4*>(&sm.t.Bs[kk][tx * 4]);
                float a[4] = {aq.x, aq.y, aq.z, aq.w};
                float c[4] = {bn.x, bn.y, bn.z, bn.w};
                #pragma unroll
                for (int i = 0; i < 4; ++i)
                    #pragma unroll
                    for (int j = 0; j < 4; ++j)
                        acc[i][j] = fmaf(a[i], c[j], acc[i][j]);
            }
            __syncthreads();
        }

        // top-3 update with s = x2 - 2*dot
        #pragma unroll
        for (int j = 0; j < 4; ++j) {
            int n = n0 + tx * 4 + j;
            if (n < NDB) {
                float xn2 = g_x2[n];
                #pragma unroll
                for (int i = 0; i < 4; ++i) {
                    float s = fmaf(-2.f, acc[i][j], xn2);
                    insert3(s, best[i][0], best[i][1], best[i][2]);
                }
            }
        }
    }

    __syncthreads();   // done with As/Bs, union switches to merge buffer
    #pragma unroll
    for (int i = 0; i < 4; ++i) {
        int ql = ty * 4 + i;
        sm.merge[ql][tx][0] = best[i][0];
        sm.merge[ql][tx][1] = best[i][1];
        sm.merge[ql][tx][2] = best[i][2];
    }
    __syncthreads();

    if (tid < QT) {
        float b0 = FLT_MAX, b1 = FLT_MAX, b2 = FLT_MAX;
        #pragma unroll 4
        for (int c = 0; c < 16; ++c) {
            insert3(sm.merge[tid][c][0], b0, b1, b2);
            insert3(sm.merge[tid][c][1], b0, b1, b2);
            insert3(sm.merge[tid][c][2], b0, b1, b2);
        }
        int q = q0 + tid;
        float* dst = &g_partial[((size_t)q * NCHUNKS + blockIdx.y) * 3];
        dst[0] = b0; dst[1] = b1; dst[2] = b2;
    }
}

// ---------------------------------------------------------------------------
// Merge partial top-3 across chunks, add ||q||^2, sqrt, mean -> ood[4,32,32]
// ---------------------------------------------------------------------------
__global__ void knn_merge_kernel() {
    int q = blockIdx.x * blockDim.x + threadIdx.x;
    if (q >= NQ) return;
    const float* p = &g_partial[(size_t)q * NCHUNKS * 3];
    float b0 = FLT_MAX, b1 = FLT_MAX, b2 = FLT_MAX;
    #pragma unroll
    for (int c = 0; c < NCHUNKS * 3; ++c)
        insert3(p[c], b0, b1, b2);
    float q2 = g_q2[q];
    float d0 = sqrtf(fmaxf(q2 + b0, 1e-12f));
    float d1 = sqrtf(fmaxf(q2 + b1, 1e-12f));
    float d2 = sqrtf(fmaxf(q2 + b2, 1e-12f));
    g_ood[q] = (d0 + d1 + d2) * (1.f / 3.f);
}

// ---------------------------------------------------------------------------
// Bilinear upsample 32x32 -> 512x512, half-pixel, edge-clamped
// (matches jax.image.resize / F.interpolate align_corners=False for upsampling)
// ---------------------------------------------------------------------------
__global__ void upsample_kernel(float* __restrict__ out) {
    int idx = blockIdx.x * blockDim.x + threadIdx.x;
    if (idx >= NB * OUT_H * OUT_W) return;
    int b   = idx >> 18;          // 512*512 = 2^18
    int rem = idx & 262143;
    int oy  = rem >> 9;
    int ox  = rem & 511;

    const float inv = 1.f / 16.f;
    float sy = (oy + 0.5f) * inv - 0.5f;
    float sx = (ox + 0.5f) * inv - 0.5f;
    float fy0 = floorf(sy), fx0 = floorf(sx);
    float fy = sy - fy0,    fx = sx - fx0;
    int y0 = (int)fy0, x0 = (int)fx0;
    int y0c = min(max(y0, 0), 31);
    int y1c = min(max(y0 + 1, 0), 31);
    int x0c = min(max(x0, 0), 31);
    int x1c = min(max(x0 + 1, 0), 31);

    const float* o = &g_ood[b * HW];
    float v00 = o[y0c * 32 + x0c];
    float v01 = o[y0c * 32 + x1c];
    float v10 = o[y1c * 32 + x0c];
    float v11 = o[y1c * 32 + x1c];
    float top = v00 + (v01 - v00) * fx;
    float bot = v10 + (v11 - v10) * fx;
    out[idx] = top + (bot - top) * fy;
}

// ---------------------------------------------------------------------------
extern "C" void kernel_launch(void* const* d_in, const int* in_sizes, int n_in,
                              void* d_out, int out_size) {
    const float* emb = (const float*)d_in[0];   // [4, 768, 32, 32]
    const float* db  = (const float*)d_in[1];   // [20000, 768]
    float* out = (float*)d_out;                 // [4, 1, 512, 512]

    db_norms_kernel<<<(NDB + 7) / 8, 256>>>(db);        // 8 warps/block
    q_norms_kernel<<<NQ / 256, 256>>>(emb);

    dim3 grid(NQ / QT, NCHUNKS);
    knn_gemm_kernel<<<grid, 256>>>(emb, db);

    knn_merge_kernel<<<(NQ + 255) / 256, 256>>>();
    upsample_kernel<<<(NB * OUT_H * OUT_W + 255) / 256, 256>>>(out);
}

// round 7
// speedup vs baseline: 8.2026x; 8.2026x over previous
#include <cuda_runtime.h>
#include <cuda_bf16.h>
#include <math.h>
#include <float.h>
#include <stdint.h>

// ---------------------------------------------------------------------------
// Problem constants
// ---------------------------------------------------------------------------
#define D        768
#define HW       1024
#define NB       4
#define NQ       4096
#define NDB      20000
#define OUT_H    512
#define OUT_W    512

// GEMM tiling
#define TM       128             // queries per CTA
#define TN       128             // db rows per CTA
#define KT       64              // bf16 K per stage
#define NKC      (D / KT)        // 12 stages of K
#define NPAD     20224           // 158 * 128
#define NTN      (NPAD / TN)     // 158
#define NQT      (NQ / TM)       // 32
#define NSLOT    (NTN * 2)       // 316 partial slots per query (2 warp halves in N)

// SMEM: rows padded to 144B (KT*2 + 16) -> conflict-free ldmatrix, 16B aligned
#define PITCH        144
#define A_BYTES      (TM * PITCH)          // 18432
#define STAGE_BYTES  (2 * A_BYTES)         // A + B = 36864
#define SM_TOTAL     (2 * STAGE_BYTES)     // 73728 (double buffered)

// ---------------------------------------------------------------------------
// Scratch (device globals — no allocations allowed)
// ---------------------------------------------------------------------------
__device__ __nv_bfloat16 g_Abf[NQ * D];        // ~6.3 MB
__device__ __nv_bfloat16 g_Bbf[NPAD * D];      // ~31 MB (padded rows zero)
__device__ float g_x2[NDB];
__device__ float g_q2[NQ];
__device__ float g_partial[(size_t)NQ * NSLOT * 3];  // ~15.5 MB
__device__ float g_ood[NQ];

// ---------------------------------------------------------------------------
// Helpers
// ---------------------------------------------------------------------------
__device__ __forceinline__ uint32_t smem_to_u32(const void* p) {
    uint32_t a;
    asm("{ .reg .u64 t; cvta.to.shared.u64 t, %1; cvt.u32.u64 %0, t; }"
        : "=r"(a) : "l"(p));
    return a;
}

__device__ __forceinline__ void cp_async16(uint32_t dst, const void* src) {
    asm volatile("cp.async.cg.shared.global [%0], [%1], 16;"
                 :: "r"(dst), "l"(src) : "memory");
}
#define CP_COMMIT() asm volatile("cp.async.commit_group;" ::: "memory")
#define CP_WAIT_1() asm volatile("cp.async.wait_group 1;" ::: "memory")
#define CP_WAIT_0() asm volatile("cp.async.wait_group 0;" ::: "memory")

__device__ __forceinline__ void ldsm_x4(uint32_t& r0, uint32_t& r1,
                                        uint32_t& r2, uint32_t& r3,
                                        uint32_t addr) {
    asm volatile("ldmatrix.sync.aligned.m8n8.x4.shared.b16 {%0,%1,%2,%3}, [%4];"
                 : "=r"(r0), "=r"(r1), "=r"(r2), "=r"(r3) : "r"(addr));
}

__device__ __forceinline__ void mma_bf16(float* c, const uint32_t* a,
                                         const uint32_t* b) {
    asm volatile(
        "mma.sync.aligned.m16n8k16.row.col.f32.bf16.bf16.f32 "
        "{%0,%1,%2,%3}, {%4,%5,%6,%7}, {%8,%9}, {%0,%1,%2,%3};"
        : "+f"(c[0]), "+f"(c[1]), "+f"(c[2]), "+f"(c[3])
        : "r"(a[0]), "r"(a[1]), "r"(a[2]), "r"(a[3]), "r"(b[0]), "r"(b[1]));
}

__device__ __forceinline__ void insert3(float s, float& b0, float& b1, float& b2) {
    if (s < b2) {
        if (s < b1) {
            b2 = b1;
            if (s < b0) { b1 = b0; b0 = s; }
            else        { b1 = s; }
        } else {
            b2 = s;
        }
    }
}

// ---------------------------------------------------------------------------
// Preprocess: embeddings [4,768,32,32] fp32 -> g_Abf [4096][768] bf16
// ---------------------------------------------------------------------------
__global__ void emb_convert_kernel(const float* __restrict__ emb) {
    __shared__ float tile[32][33];
    int b  = blockIdx.z;
    int d0 = blockIdx.x * 32;
    int p0 = blockIdx.y * 32;
    tile[threadIdx.y][threadIdx.x] =
        emb[(size_t)b * D * HW + (size_t)(d0 + threadIdx.y) * HW + p0 + threadIdx.x];
    __syncthreads();
    int q = b * HW + p0 + threadIdx.y;
    g_Abf[(size_t)q * D + d0 + threadIdx.x] =
        __float2bfloat16(tile[threadIdx.x][threadIdx.y]);
}

// ---------------------------------------------------------------------------
// Preprocess: db [20000][768] fp32 -> g_Bbf [20224][768] bf16 (pad rows zero)
// ---------------------------------------------------------------------------
__global__ void db_convert_kernel(const float* __restrict__ db) {
    int i = blockIdx.x * blockDim.x + threadIdx.x;   // bf16-pair index
    if (i >= NPAD * (D / 2)) return;
    int row = i / (D / 2);
    __nv_bfloat162 v;
    if (row < NDB) {
        float2 f = reinterpret_cast<const float2*>(db)[i];
        v = __floats2bfloat162_rn(f.x, f.y);
    } else {
        v = __floats2bfloat162_rn(0.f, 0.f);
    }
    reinterpret_cast<__nv_bfloat162*>(g_Bbf)[i] = v;
}

// ---------------------------------------------------------------------------
// Norms (fp32 originals)
// ---------------------------------------------------------------------------
__global__ void db_norms_kernel(const float* __restrict__ db) {
    int row  = blockIdx.x * (blockDim.x >> 5) + (threadIdx.x >> 5);
    int lane = threadIdx.x & 31;
    if (row >= NDB) return;
    const float* r = db + (size_t)row * D;
    float s = 0.f;
    #pragma unroll 4
    for (int d = lane; d < D; d += 32) { float v = r[d]; s = fmaf(v, v, s); }
    #pragma unroll
    for (int o = 16; o; o >>= 1) s += __shfl_down_sync(0xffffffffu, s, o);
    if (lane == 0) g_x2[row] = s;
}

__global__ void q_norms_kernel(const float* __restrict__ emb) {
    int q = blockIdx.x * blockDim.x + threadIdx.x;
    if (q >= NQ) return;
    int b = q >> 10;
    int p = q & 1023;
    const float* e = emb + (size_t)b * D * HW + p;
    float s = 0.f;
    #pragma unroll 8
    for (int d = 0; d < D; ++d) { float v = e[(size_t)d * HW]; s = fmaf(v, v, s); }
    g_q2[q] = s;
}

// ---------------------------------------------------------------------------
// bf16 mma.sync GEMM + fused top-3 epilogue.
// CTA: 128 q x 128 n, 8 warps (4M x 2N), warp tile 32x64.
// K streamed in 12 chunks of 64, cp.async double buffered.
// ---------------------------------------------------------------------------
__global__ void __launch_bounds__(256, 2) knn_mma_kernel() {
    extern __shared__ char smem[];
    const uint32_t smem_u = smem_to_u32(smem);
    const int tid  = threadIdx.x;
    const int lane = tid & 31;
    const int wid  = tid >> 5;
    const int wm   = wid & 3;      // warp M position (0..3)
    const int wn   = wid >> 2;     // warp N position (0..1)

    const int q0 = blockIdx.x * TM;
    const int n0 = blockIdx.y * TN;

    const __nv_bfloat16* Ag0 = g_Abf + (size_t)q0 * D;
    const __nv_bfloat16* Bg0 = g_Bbf + (size_t)n0 * D;

    const int lr = tid >> 3;   // loader row base (0..31)
    const int lc = tid & 7;    // loader 16B chunk (0..7)

    float acc[2][8][4];
    #pragma unroll
    for (int mt = 0; mt < 2; ++mt)
        #pragma unroll
        for (int nt = 0; nt < 8; ++nt)
            #pragma unroll
            for (int j = 0; j < 4; ++j) acc[mt][nt][j] = 0.f;

    auto issue_load = [&](int buf, int kc) {
        uint32_t baseA = smem_u + buf * STAGE_BYTES;
        uint32_t baseB = baseA + A_BYTES;
        const __nv_bfloat16* Asrc = Ag0 + kc * KT;
        const __nv_bfloat16* Bsrc = Bg0 + kc * KT;
        #pragma unroll
        for (int i = 0; i < 4; ++i) {
            int r = lr + i * 32;
            cp_async16(baseA + r * PITCH + lc * 16, Asrc + (size_t)r * D + lc * 8);
        }
        #pragma unroll
        for (int i = 0; i < 4; ++i) {
            int r = lr + i * 32;
            cp_async16(baseB + r * PITCH + lc * 16, Bsrc + (size_t)r * D + lc * 8);
        }
    };

    // ldmatrix address components
    const int a_row  = wm * 32 + (lane & 15);
    const int a_kadd = (lane >> 4) * 8;
    const int b_row  = wn * 64 + ((lane >> 4) & 1) * 8 + (lane & 7);
    const int b_kadd = ((lane >> 3) & 1) * 8;

    issue_load(0, 0); CP_COMMIT();
    issue_load(1, 1); CP_COMMIT();

    for (int s = 0; s < NKC; ++s) {
        if (s + 1 < NKC) { CP_WAIT_1(); } else { CP_WAIT_0(); }
        __syncthreads();

        const int buf = s & 1;
        const uint32_t aBase = smem_u + buf * STAGE_BYTES;
        const uint32_t bBase = aBase + A_BYTES;

        #pragma unroll
        for (int kk = 0; kk < 4; ++kk) {
            uint32_t aF[2][4];
            #pragma unroll
            for (int mt = 0; mt < 2; ++mt) {
                uint32_t addr = aBase + (a_row + mt * 16) * PITCH
                              + (kk * 16 + a_kadd) * 2;
                ldsm_x4(aF[mt][0], aF[mt][1], aF[mt][2], aF[mt][3], addr);
            }
            uint32_t bF[8][2];
            #pragma unroll
            for (int p = 0; p < 4; ++p) {
                uint32_t addr = bBase + (b_row + p * 16) * PITCH
                              + (kk * 16 + b_kadd) * 2;
                uint32_t r0, r1, r2, r3;
                ldsm_x4(r0, r1, r2, r3, addr);
                bF[2 * p][0]     = r0;
                bF[2 * p][1]     = r1;
                bF[2 * p + 1][0] = r2;
                bF[2 * p + 1][1] = r3;
            }
            #pragma unroll
            for (int mt = 0; mt < 2; ++mt)
                #pragma unroll
                for (int nt = 0; nt < 8; ++nt)
                    mma_bf16(acc[mt][nt], aF[mt], bF[nt]);
        }

        __syncthreads();
        if (s + 2 < NKC) { issue_load(buf, s + 2); CP_COMMIT(); }
    }

    // -----------------------------------------------------------------------
    // Epilogue: s = ||x||^2 - 2*dot ; per-thread top3 ; quad merge ; write
    // Fragment c: row = lane/4 (+8 for c2,c3), cols = (lane%4)*2 + {0,1}
    // -----------------------------------------------------------------------
    const int lane4 = lane & 3;
    const int quad  = lane >> 2;

    float xn2[8][2];
    #pragma unroll
    for (int nt = 0; nt < 8; ++nt)
        #pragma unroll
        for (int j = 0; j < 2; ++j) {
            int n = n0 + wn * 64 + nt * 8 + lane4 * 2 + j;
            xn2[nt][j] = (n < NDB) ? g_x2[n] : FLT_MAX;
        }

    #pragma unroll
    for (int mt = 0; mt < 2; ++mt) {
        #pragma unroll
        for (int half = 0; half < 2; ++half) {
            float b0 = FLT_MAX, b1 = FLT_MAX, b2 = FLT_MAX;
            #pragma unroll
            for (int nt = 0; nt < 8; ++nt) {
                #pragma unroll
                for (int j = 0; j < 2; ++j) {
                    float v = fmaf(-2.f, acc[mt][nt][half * 2 + j], xn2[nt][j]);
                    insert3(v, b0, b1, b2);
                }
            }
            // merge across the 4 lanes of the quad (same query row)
            #pragma unroll
            for (int o = 1; o <= 2; o <<= 1) {
                float t0 = __shfl_xor_sync(0xffffffffu, b0, o);
                float t1 = __shfl_xor_sync(0xffffffffu, b1, o);
                float t2 = __shfl_xor_sync(0xffffffffu, b2, o);
                insert3(t0, b0, b1, b2);
                insert3(t1, b0, b1, b2);
                insert3(t2, b0, b1, b2);
            }
            if (lane4 == 0) {
                int q = q0 + wm * 32 + mt * 16 + quad + half * 8;
                float* dst = g_partial
                    + ((size_t)q * NSLOT + blockIdx.y * 2 + wn) * 3;
                dst[0] = b0; dst[1] = b1; dst[2] = b2;
            }
        }
    }
}

// ---------------------------------------------------------------------------
// Merge partials (warp per query), add ||q||^2, sqrt, mean
// ---------------------------------------------------------------------------
__global__ void knn_merge_kernel() {
    int warp = (blockIdx.x * blockDim.x + threadIdx.x) >> 5;
    int lane = threadIdx.x & 31;
    if (warp >= NQ) return;
    const float* p = g_partial + (size_t)warp * NSLOT * 3;
    float b0 = FLT_MAX, b1 = FLT_MAX, b2 = FLT_MAX;
    for (int i = lane; i < NSLOT * 3; i += 32)
        insert3(p[i], b0, b1, b2);
    #pragma unroll
    for (int o = 16; o; o >>= 1) {
        float t0 = __shfl_xor_sync(0xffffffffu, b0, o);
        float t1 = __shfl_xor_sync(0xffffffffu, b1, o);
        float t2 = __shfl_xor_sync(0xffffffffu, b2, o);
        insert3(t0, b0, b1, b2);
        insert3(t1, b0, b1, b2);
        insert3(t2, b0, b1, b2);
    }
    if (lane == 0) {
        float q2 = g_q2[warp];
        float d0 = sqrtf(fmaxf(q2 + b0, 1e-12f));
        float d1 = sqrtf(fmaxf(q2 + b1, 1e-12f));
        float d2 = sqrtf(fmaxf(q2 + b2, 1e-12f));
        g_ood[warp] = (d0 + d1 + d2) * (1.f / 3.f);
    }
}

// ---------------------------------------------------------------------------
// Bilinear upsample 32x32 -> 512x512 (half-pixel, edge-clamped)
// ---------------------------------------------------------------------------
__global__ void upsample_kernel(float* __restrict__ out) {
    int idx = blockIdx.x * blockDim.x + threadIdx.x;
    if (idx >= NB * OUT_H * OUT_W) return;
    int b   = idx >> 18;
    int rem = idx & 262143;
    int oy  = rem >> 9;
    int ox  = rem & 511;

    const float inv = 1.f / 16.f;
    float sy = (oy + 0.5f) * inv - 0.5f;
    float sx = (ox + 0.5f) * inv - 0.5f;
    float fy0 = floorf(sy), fx0 = floorf(sx);
    float fy = sy - fy0,    fx = sx - fx0;
    int y0 = (int)fy0, x0 = (int)fx0;
    int y0c = min(max(y0, 0), 31);
    int y1c = min(max(y0 + 1, 0), 31);
    int x0c = min(max(x0, 0), 31);
    int x1c = min(max(x0 + 1, 0), 31);

    const float* o = &g_ood[b * HW];
    float v00 = o[y0c * 32 + x0c];
    float v01 = o[y0c * 32 + x1c];
    float v10 = o[y1c * 32 + x0c];
    float v11 = o[y1c * 32 + x1c];
    float top = v00 + (v01 - v00) * fx;
    float bot = v10 + (v11 - v10) * fx;
    out[idx] = top + (bot - top) * fy;
}

// ---------------------------------------------------------------------------
extern "C" void kernel_launch(void* const* d_in, const int* in_sizes, int n_in,
                              void* d_out, int out_size) {
    const float* emb = (const float*)d_in[0];   // [4, 768, 32, 32]
    const float* db  = (const float*)d_in[1];   // [20000, 768]
    float* out = (float*)d_out;                 // [4, 1, 512, 512]

    cudaFuncSetAttribute(knn_mma_kernel,
                         cudaFuncAttributeMaxDynamicSharedMemorySize, SM_TOTAL);

    dim3 tgrid(D / 32, HW / 32, NB);
    emb_convert_kernel<<<tgrid, dim3(32, 32)>>>(emb);

    int pairs = NPAD * (D / 2);
    db_convert_kernel<<<(pairs + 255) / 256, 256>>>(db);

    db_norms_kernel<<<(NDB + 7) / 8, 256>>>(db);
    q_norms_kernel<<<NQ / 256, 256>>>(emb);

    dim3 grid(NQT, NTN);
    knn_mma_kernel<<<grid, 256, SM_TOTAL>>>();

    knn_merge_kernel<<<(NQ * 32 + 255) / 256, 256>>>();
    upsample_kernel<<<(NB * OUT_H * OUT_W + 255) / 256, 256>>>(out);
}

// round 8
// speedup vs baseline: 9.9547x; 1.2136x over previous
#include <cuda_runtime.h>
#include <cuda_bf16.h>
#include <math.h>
#include <float.h>
#include <stdint.h>

// ---------------------------------------------------------------------------
// Problem constants
// ---------------------------------------------------------------------------
#define D        768
#define HW       1024
#define NB       4
#define NQ       4096
#define NDB      20000
#define OUT_H    512
#define OUT_W    512

// GEMM tiling
#define TM       128             // queries per CTA
#define TN       128             // db rows per CTA
#define KT       64              // bf16 K per stage
#define NKC      (D / KT)        // 12 K-stages
#define NPAD     20096           // 157 * 128
#define NTN      (NPAD / TN)     // 157
#define NQT      (NQ / TM)       // 32
#define NSLOT    (NTN * 2)       // partial slots per query (2 warp halves in N)

// SMEM: rows padded to 144B -> conflict-free ldmatrix, 16B aligned
#define PITCH        144
#define A_BYTES      (TM * PITCH)          // 18432
#define STAGE_BYTES  (2 * A_BYTES)         // A + B = 36864
#define NSTAGE       3
#define SM_TOTAL     (NSTAGE * STAGE_BYTES)  // 110592

// ---------------------------------------------------------------------------
// Scratch (device globals — no allocations allowed)
// ---------------------------------------------------------------------------
__device__ __nv_bfloat16 g_Abf[NQ * D];        // ~6.3 MB
__device__ __nv_bfloat16 g_Bbf[NPAD * D];      // ~31 MB (padded rows zero)
__device__ float g_x2[NDB];
__device__ float g_q2[NQ];
__device__ float g_partial[(size_t)NQ * NSLOT * 3];  // ~15.4 MB
__device__ float g_ood[NQ];

// ---------------------------------------------------------------------------
// Helpers
// ---------------------------------------------------------------------------
__device__ __forceinline__ uint32_t smem_to_u32(const void* p) {
    uint32_t a;
    asm("{ .reg .u64 t; cvta.to.shared.u64 t, %1; cvt.u32.u64 %0, t; }"
        : "=r"(a) : "l"(p));
    return a;
}

__device__ __forceinline__ void cp_async16(uint32_t dst, const void* src) {
    asm volatile("cp.async.cg.shared.global [%0], [%1], 16;"
                 :: "r"(dst), "l"(src) : "memory");
}
#define CP_COMMIT() asm volatile("cp.async.commit_group;" ::: "memory")
#define CP_WAIT_1() asm volatile("cp.async.wait_group 1;" ::: "memory")
#define CP_WAIT_0() asm volatile("cp.async.wait_group 0;" ::: "memory")

__device__ __forceinline__ void ldsm_x4(uint32_t& r0, uint32_t& r1,
                                        uint32_t& r2, uint32_t& r3,
                                        uint32_t addr) {
    asm volatile("ldmatrix.sync.aligned.m8n8.x4.shared.b16 {%0,%1,%2,%3}, [%4];"
                 : "=r"(r0), "=r"(r1), "=r"(r2), "=r"(r3) : "r"(addr));
}

__device__ __forceinline__ void mma_bf16(float* c, const uint32_t* a,
                                         const uint32_t* b) {
    asm volatile(
        "mma.sync.aligned.m16n8k16.row.col.f32.bf16.bf16.f32 "
        "{%0,%1,%2,%3}, {%4,%5,%6,%7}, {%8,%9}, {%0,%1,%2,%3};"
        : "+f"(c[0]), "+f"(c[1]), "+f"(c[2]), "+f"(c[3])
        : "r"(a[0]), "r"(a[1]), "r"(a[2]), "r"(a[3]), "r"(b[0]), "r"(b[1]));
}

__device__ __forceinline__ void insert3(float s, float& b0, float& b1, float& b2) {
    if (s < b2) {
        if (s < b1) {
            b2 = b1;
            if (s < b0) { b1 = b0; b0 = s; }
            else        { b1 = s; }
        } else {
            b2 = s;
        }
    }
}

// ---------------------------------------------------------------------------
// Preprocess: embeddings [4,768,32,32] fp32 -> g_Abf [4096][768] bf16
// ---------------------------------------------------------------------------
__global__ void emb_convert_kernel(const float* __restrict__ emb) {
    __shared__ float tile[32][33];
    int b  = blockIdx.z;
    int d0 = blockIdx.x * 32;
    int p0 = blockIdx.y * 32;
    tile[threadIdx.y][threadIdx.x] =
        emb[(size_t)b * D * HW + (size_t)(d0 + threadIdx.y) * HW + p0 + threadIdx.x];
    __syncthreads();
    int q = b * HW + p0 + threadIdx.y;
    g_Abf[(size_t)q * D + d0 + threadIdx.x] =
        __float2bfloat16(tile[threadIdx.x][threadIdx.y]);
}

// ---------------------------------------------------------------------------
// Query norms from bf16 rows (contiguous, coalesced): warp per query
// ---------------------------------------------------------------------------
__global__ void q_norms_bf_kernel() {
    int warp = (blockIdx.x * blockDim.x + threadIdx.x) >> 5;
    int lane = threadIdx.x & 31;
    if (warp >= NQ) return;
    const __nv_bfloat162* row =
        reinterpret_cast<const __nv_bfloat162*>(g_Abf + (size_t)warp * D);
    float s = 0.f;
    #pragma unroll
    for (int i = lane; i < D / 2; i += 32) {
        float2 f = __bfloat1622float2(row[i]);
        s = fmaf(f.x, f.x, fmaf(f.y, f.y, s));
    }
    #pragma unroll
    for (int o = 16; o; o >>= 1) s += __shfl_down_sync(0xffffffffu, s, o);
    if (lane == 0) g_q2[warp] = s;
}

// ---------------------------------------------------------------------------
// Fused db preprocess: fp32 [20000][768] -> bf16 padded [20096][768] + norms
// One warp per row; reads db exactly once.
// ---------------------------------------------------------------------------
__global__ void db_prep_kernel(const float* __restrict__ db) {
    int row  = blockIdx.x * (blockDim.x >> 5) + (threadIdx.x >> 5);
    int lane = threadIdx.x & 31;
    if (row >= NPAD) return;
    __nv_bfloat162* dst =
        reinterpret_cast<__nv_bfloat162*>(g_Bbf + (size_t)row * D);
    if (row < NDB) {
        const float2* src = reinterpret_cast<const float2*>(db + (size_t)row * D);
        float s = 0.f;
        #pragma unroll
        for (int i = lane; i < D / 2; i += 32) {
            float2 f = src[i];
            s = fmaf(f.x, f.x, fmaf(f.y, f.y, s));
            dst[i] = __floats2bfloat162_rn(f.x, f.y);
        }
        #pragma unroll
        for (int o = 16; o; o >>= 1) s += __shfl_down_sync(0xffffffffu, s, o);
        if (lane == 0) g_x2[row] = s;
    } else {
        __nv_bfloat162 z = __floats2bfloat162_rn(0.f, 0.f);
        #pragma unroll
        for (int i = lane; i < D / 2; i += 32) dst[i] = z;
    }
}

// ---------------------------------------------------------------------------
// bf16 mma.sync GEMM + fused top-3 epilogue.
// CTA: 128 q x 128 n, 8 warps (4M x 2N), warp tile 32x64.
// K streamed in 12 chunks of 64; 3-stage cp.async pipeline, 1 barrier/stage.
// ---------------------------------------------------------------------------
__global__ void __launch_bounds__(256, 2) knn_mma_kernel() {
    extern __shared__ char smem[];
    const uint32_t smem_u = smem_to_u32(smem);
    const int tid  = threadIdx.x;
    const int lane = tid & 31;
    const int wid  = tid >> 5;
    const int wm   = wid & 3;      // warp M position (0..3)
    const int wn   = wid >> 2;     // warp N position (0..1)

    const int q0 = blockIdx.x * TM;
    const int n0 = blockIdx.y * TN;

    const __nv_bfloat16* Ag0 = g_Abf + (size_t)q0 * D;
    const __nv_bfloat16* Bg0 = g_Bbf + (size_t)n0 * D;

    const int lr = tid >> 3;   // loader row base (0..31)
    const int lc = tid & 7;    // loader 16B chunk (0..7)

    float acc[2][8][4];
    #pragma unroll
    for (int mt = 0; mt < 2; ++mt)
        #pragma unroll
        for (int nt = 0; nt < 8; ++nt)
            #pragma unroll
            for (int j = 0; j < 4; ++j) acc[mt][nt][j] = 0.f;

    auto issue_load = [&](int buf, int kc) {
        uint32_t baseA = smem_u + buf * STAGE_BYTES;
        uint32_t baseB = baseA + A_BYTES;
        const __nv_bfloat16* Asrc = Ag0 + kc * KT;
        const __nv_bfloat16* Bsrc = Bg0 + kc * KT;
        #pragma unroll
        for (int i = 0; i < 4; ++i) {
            int r = lr + i * 32;
            cp_async16(baseA + r * PITCH + lc * 16, Asrc + (size_t)r * D + lc * 8);
        }
        #pragma unroll
        for (int i = 0; i < 4; ++i) {
            int r = lr + i * 32;
            cp_async16(baseB + r * PITCH + lc * 16, Bsrc + (size_t)r * D + lc * 8);
        }
    };

    // ldmatrix address components
    const int a_row  = wm * 32 + (lane & 15);
    const int a_kadd = (lane >> 4) * 8;
    const int b_row  = wn * 64 + ((lane >> 4) & 1) * 8 + (lane & 7);
    const int b_kadd = ((lane >> 3) & 1) * 8;

    issue_load(0, 0); CP_COMMIT();
    issue_load(1, 1); CP_COMMIT();

    int buf = 0;        // stage s % 3
    int nbuf = 2;       // (s+2) % 3
    for (int s = 0; s < NKC; ++s) {
        if (s + 1 < NKC) { CP_WAIT_1(); } else { CP_WAIT_0(); }
        __syncthreads();   // stage-s data visible; stage-(s-1) buffer drained

        if (s + 2 < NKC) { issue_load(nbuf, s + 2); CP_COMMIT(); }

        const uint32_t aBase = smem_u + buf * STAGE_BYTES;
        const uint32_t bBase = aBase + A_BYTES;

        #pragma unroll
        for (int kk = 0; kk < 4; ++kk) {
            uint32_t aF[2][4];
            #pragma unroll
            for (int mt = 0; mt < 2; ++mt) {
                uint32_t addr = aBase + (a_row + mt * 16) * PITCH
                              + (kk * 16 + a_kadd) * 2;
                ldsm_x4(aF[mt][0], aF[mt][1], aF[mt][2], aF[mt][3], addr);
            }
            uint32_t bF[8][2];
            #pragma unroll
            for (int p = 0; p < 4; ++p) {
                uint32_t addr = bBase + (b_row + p * 16) * PITCH
                              + (kk * 16 + b_kadd) * 2;
                uint32_t r0, r1, r2, r3;
                ldsm_x4(r0, r1, r2, r3, addr);
                bF[2 * p][0]     = r0;
                bF[2 * p][1]     = r1;
                bF[2 * p + 1][0] = r2;
                bF[2 * p + 1][1] = r3;
            }
            #pragma unroll
            for (int mt = 0; mt < 2; ++mt)
                #pragma unroll
                for (int nt = 0; nt < 8; ++nt)
                    mma_bf16(acc[mt][nt], aF[mt], bF[nt]);
        }

        buf  = (buf  == 2) ? 0 : buf + 1;
        nbuf = (nbuf == 2) ? 0 : nbuf + 1;
    }

    // -----------------------------------------------------------------------
    // Epilogue: s = ||x||^2 - 2*dot ; per-thread top3 ; quad merge ; write
    // Fragment c: row = lane/4 (+8 for c2,c3), cols = (lane%4)*2 + {0,1}
    // -----------------------------------------------------------------------
    const int lane4 = lane & 3;
    const int quad  = lane >> 2;

    float xn2[8][2];
    #pragma unroll
    for (int nt = 0; nt < 8; ++nt)
        #pragma unroll
        for (int j = 0; j < 2; ++j) {
            int n = n0 + wn * 64 + nt * 8 + lane4 * 2 + j;
            xn2[nt][j] = (n < NDB) ? g_x2[n] : FLT_MAX;
        }

    #pragma unroll
    for (int mt = 0; mt < 2; ++mt) {
        #pragma unroll
        for (int half = 0; half < 2; ++half) {
            float b0 = FLT_MAX, b1 = FLT_MAX, b2 = FLT_MAX;
            #pragma unroll
            for (int nt = 0; nt < 8; ++nt) {
                #pragma unroll
                for (int j = 0; j < 2; ++j) {
                    float v = fmaf(-2.f, acc[mt][nt][half * 2 + j], xn2[nt][j]);
                    insert3(v, b0, b1, b2);
                }
            }
            #pragma unroll
            for (int o = 1; o <= 2; o <<= 1) {
                float t0 = __shfl_xor_sync(0xffffffffu, b0, o);
                float t1 = __shfl_xor_sync(0xffffffffu, b1, o);
                float t2 = __shfl_xor_sync(0xffffffffu, b2, o);
                insert3(t0, b0, b1, b2);
                insert3(t1, b0, b1, b2);
                insert3(t2, b0, b1, b2);
            }
            if (lane4 == 0) {
                int q = q0 + wm * 32 + mt * 16 + quad + half * 8;
                float* dst = g_partial
                    + ((size_t)q * NSLOT + blockIdx.y * 2 + wn) * 3;
                dst[0] = b0; dst[1] = b1; dst[2] = b2;
            }
        }
    }
}

// ---------------------------------------------------------------------------
// Merge partials (warp per query), add ||q||^2, sqrt, mean
// ---------------------------------------------------------------------------
__global__ void knn_merge_kernel() {
    int warp = (blockIdx.x * blockDim.x + threadIdx.x) >> 5;
    int lane = threadIdx.x & 31;
    if (warp >= NQ) return;
    const float* p = g_partial + (size_t)warp * NSLOT * 3;
    float b0 = FLT_MAX, b1 = FLT_MAX, b2 = FLT_MAX;
    for (int i = lane; i < NSLOT * 3; i += 32)
        insert3(p[i], b0, b1, b2);
    #pragma unroll
    for (int o = 16; o; o >>= 1) {
        float t0 = __shfl_xor_sync(0xffffffffu, b0, o);
        float t1 = __shfl_xor_sync(0xffffffffu, b1, o);
        float t2 = __shfl_xor_sync(0xffffffffu, b2, o);
        insert3(t0, b0, b1, b2);
        insert3(t1, b0, b1, b2);
        insert3(t2, b0, b1, b2);
    }
    if (lane == 0) {
        float q2 = g_q2[warp];
        float d0 = sqrtf(fmaxf(q2 + b0, 1e-12f));
        float d1 = sqrtf(fmaxf(q2 + b1, 1e-12f));
        float d2 = sqrtf(fmaxf(q2 + b2, 1e-12f));
        g_ood[warp] = (d0 + d1 + d2) * (1.f / 3.f);
    }
}

// ---------------------------------------------------------------------------
// Bilinear upsample 32x32 -> 512x512 (half-pixel, edge-clamped)
// ---------------------------------------------------------------------------
__global__ void upsample_kernel(float* __restrict__ out) {
    int idx = blockIdx.x * blockDim.x + threadIdx.x;
    if (idx >= NB * OUT_H * OUT_W) return;
    int b   = idx >> 18;
    int rem = idx & 262143;
    int oy  = rem >> 9;
    int ox  = rem & 511;

    const float inv = 1.f / 16.f;
    float sy = (oy + 0.5f) * inv - 0.5f;
    float sx = (ox + 0.5f) * inv - 0.5f;
    float fy0 = floorf(sy), fx0 = floorf(sx);
    float fy = sy - fy0,    fx = sx - fx0;
    int y0 = (int)fy0, x0 = (int)fx0;
    int y0c = min(max(y0, 0), 31);
    int y1c = min(max(y0 + 1, 0), 31);
    int x0c = min(max(x0, 0), 31);
    int x1c = min(max(x0 + 1, 0), 31);

    const float* o = &g_ood[b * HW];
    float v00 = o[y0c * 32 + x0c];
    float v01 = o[y0c * 32 + x1c];
    float v10 = o[y1c * 32 + x0c];
    float v11 = o[y1c * 32 + x1c];
    float top = v00 + (v01 - v00) * fx;
    float bot = v10 + (v11 - v10) * fx;
    out[idx] = top + (bot - top) * fy;
}

// ---------------------------------------------------------------------------
extern "C" void kernel_launch(void* const* d_in, const int* in_sizes, int n_in,
                              void* d_out, int out_size) {
    const float* emb = (const float*)d_in[0];   // [4, 768, 32, 32]
    const float* db  = (const float*)d_in[1];   // [20000, 768]
    float* out = (float*)d_out;                 // [4, 1, 512, 512]

    cudaFuncSetAttribute(knn_mma_kernel,
                         cudaFuncAttributeMaxDynamicSharedMemorySize, SM_TOTAL);

    dim3 tgrid(D / 32, HW / 32, NB);
    emb_convert_kernel<<<tgrid, dim3(32, 32)>>>(emb);

    q_norms_bf_kernel<<<(NQ * 32) / 256, 256>>>();          // 512 blocks
    db_prep_kernel<<<(NPAD + 7) / 8, 256>>>(db);            // warp per row

    dim3 grid(NQT, NTN);
    knn_mma_kernel<<<grid, 256, SM_TOTAL>>>();

    knn_merge_kernel<<<(NQ * 32 + 255) / 256, 256>>>();
    upsample_kernel<<<(NB * OUT_H * OUT_W + 255) / 256, 256>>>(out);
}